// round 13
// baseline (speedup 1.0000x reference)
#include <cuda_runtime.h>
#include <cuda_bf16.h>

#define SL 1024
#define NE 4
#define ND 128
#define NBATCH 4
#define KA (SL*NE)

typedef unsigned long long u64;
typedef unsigned int u32;

// ---- scratch (no allocs allowed) ----
__device__ __align__(128) float g_pi[(size_t)NBATCH*KA*ND];
__device__ __align__(128) float g_po[(size_t)NBATCH*KA*ND];
__device__ __align__(128) float g_ni[(size_t)NBATCH*SL*ND];
__device__ __align__(128) float g_no[(size_t)NBATCH*SL*ND];
__device__ __align__(128) float g_st[(size_t)NBATCH*SL*ND];

// ---- packed f32x2 helpers ----
__device__ __forceinline__ u64 pk2(float a, float b){
    u64 r; asm("mov.b64 %0,{%1,%2};":"=l"(r):"r"(__float_as_uint(a)),"r"(__float_as_uint(b))); return r;
}
__device__ __forceinline__ void upk2(u64 v, float&a, float&b){
    u32 lo,hi; asm("mov.b64 {%0,%1},%2;":"=r"(lo),"=r"(hi):"l"(v));
    a=__uint_as_float(lo); b=__uint_as_float(hi);
}
__device__ __forceinline__ void fma2(u64&d, u64 a, u64 b){
    asm("fma.rn.f32x2 %0,%1,%2,%0;":"+l"(d):"l"(a),"l"(b));
}
__device__ __forceinline__ float sigm(float v){ return 1.f/(1.f+__expf(-v)); }

__device__ __forceinline__ u32 smem_u32(const void* p){
    u32 a; asm("{ .reg .u64 t; cvta.to.shared.u64 t,%1; cvt.u32.u64 %0,t; }":"=r"(a):"l"(p));
    return a;
}
__device__ __forceinline__ void cpa16(u32 dst, const void* src){
    asm volatile("cp.async.cg.shared.global [%0],[%1],16;"::"r"(dst),"l"(src));
}
__device__ __forceinline__ void cpa_commit(){ asm volatile("cp.async.commit_group;"); }
__device__ __forceinline__ void cpa_wait0(){ asm volatile("cp.async.wait_group 0;"); }
__device__ __forceinline__ void cpa_wait1(){ asm volatile("cp.async.wait_group 1;"); }
__device__ __forceinline__ void cpa_wait2(){ asm volatile("cp.async.wait_group 2;"); }

struct Smem32 { u64 A2[16][32]; float Bs[16][128]; };        // 12 KB  (gru, 128 thr)
struct GSmem32 { Smem32 g; float ro[32][ND]; };              // 28 KB

// ---- 32-row FFMA2 core (gru; verified round 12; untouched) ----
template<int NT>
__device__ __forceinline__ void gemm32(
    const float* a0, const float* a1, const float* a2,
    const float* __restrict__ Bmat, u64 (&acc)[4][4], Smem32& sm)
{
    const int tid=threadIdx.x;
    const int r0=(tid>>4)*4, c0=(tid&15)*8;
    const int arow=tid>>2, ac=(tid&3)*4;
    const int bw=tid>>5, bc=(tid&31)*4;
    float4 ra,rb0,rb1,rb2,rb3;
    ra  = *(const float4*)(a0 + (size_t)arow*ND + ac);
    rb0 = *(const float4*)(Bmat + bw*ND + bc);
    rb1 = *(const float4*)(Bmat + (bw+4)*ND + bc);
    rb2 = *(const float4*)(Bmat + (bw+8)*ND + bc);
    rb3 = *(const float4*)(Bmat + (bw+12)*ND + bc);
#pragma unroll 1
    for (int kt=0; kt<NT; ++kt){
        sm.A2[ac+0][arow]=pk2(ra.x,ra.x); sm.A2[ac+1][arow]=pk2(ra.y,ra.y);
        sm.A2[ac+2][arow]=pk2(ra.z,ra.z); sm.A2[ac+3][arow]=pk2(ra.w,ra.w);
        *(float4*)&sm.Bs[bw][bc]   =rb0;
        *(float4*)&sm.Bs[bw+4][bc] =rb1;
        *(float4*)&sm.Bs[bw+8][bc] =rb2;
        *(float4*)&sm.Bs[bw+12][bc]=rb3;
        __syncthreads();
        if (kt+1<NT){
            const int kn=kt+1;
            const float* ap=(kn<8)?a0:((kn<16)?a1:a2);
            const int off=(kn&7)*16;
            ra = *(const float4*)(ap + (size_t)arow*ND + off + ac);
            const float* bp = Bmat + (size_t)kn*16*ND;
            rb0 = *(const float4*)(bp + bw*ND + bc);
            rb1 = *(const float4*)(bp + (bw+4)*ND + bc);
            rb2 = *(const float4*)(bp + (bw+8)*ND + bc);
            rb3 = *(const float4*)(bp + (bw+12)*ND + bc);
        }
#pragma unroll
        for (int kk=0;kk<16;++kk){
            u64 a0v=sm.A2[kk][r0],a1v=sm.A2[kk][r0+1],a2v=sm.A2[kk][r0+2],a3v=sm.A2[kk][r0+3];
            ulonglong2 b01=*(const ulonglong2*)&sm.Bs[kk][c0];
            ulonglong2 b23=*(const ulonglong2*)&sm.Bs[kk][c0+4];
            fma2(acc[0][0],a0v,b01.x); fma2(acc[0][1],a0v,b01.y); fma2(acc[0][2],a0v,b23.x); fma2(acc[0][3],a0v,b23.y);
            fma2(acc[1][0],a1v,b01.x); fma2(acc[1][1],a1v,b01.y); fma2(acc[1][2],a1v,b23.x); fma2(acc[1][3],a1v,b23.y);
            fma2(acc[2][0],a2v,b01.x); fma2(acc[2][1],a2v,b01.y); fma2(acc[2][2],a2v,b23.x); fma2(acc[2][3],a2v,b23.y);
            fma2(acc[3][0],a3v,b01.x); fma2(acc[3][1],a3v,b01.y); fma2(acc[3][2],a3v,b23.x); fma2(acc[3][3],a3v,b23.y);
        }
        __syncthreads();
    }
}
#define ZERO_ACC(acc) { _Pragma("unroll") for(int i=0;i<4;++i){ _Pragma("unroll") for(int j=0;j<4;++j) acc[i][j]=0ull; } }

// ---- kernel 1: proj — A staged once, 4 edge-type GEMMs per CTA, 8x4 microtile ----
// dyn smem: As[128][64] k-major fp32 (32 KB) | B ring 4 x (16x128) (32 KB)
#define PROJ_SMEM 65536
__global__ void __launch_bounds__(256) proj_kernel(
    const float* __restrict__ x,
    const float* __restrict__ W_ein, const float* __restrict__ b_ein,
    const float* __restrict__ W_eout, const float* __restrict__ b_eout, int use_x)
{
    extern __shared__ char psm[];
    float (*As)[64] = (float(*)[64])psm;                       // [128][64]
    float (*Bs)[16][128] = (float(*)[16][128])(psm + 32768);   // [4][16][128]
    const u32 bbase = smem_u32(psm + 32768);

    const int tid=threadIdx.x;
    const int stile=blockIdx.x, dir=blockIdx.y, b=blockIdx.z;
    const float* src = (use_x? x : (const float*)g_st) + (size_t)b*SL*ND + (size_t)stile*64*ND;
    const float* Wb   = dir? W_eout : W_ein;
    const float* bias0= dir? b_eout : b_ein;
    float* dst = (dir? g_po : g_pi) + (size_t)b*KA*ND;

    auto issueB = [&](int t){                // t = e*8+kt, 0..31
        const float* bp = Wb + (size_t)(t>>3)*ND*ND + (size_t)(t&7)*16*ND;
        const u32 slot = bbase + (u32)(t&3)*8192;
#pragma unroll
        for (int j=0;j<2;++j){
            const int id=tid*2+j, r=id>>5, c=id&31;
            cpa16(slot + r*512 + c*16, bp + (size_t)r*ND + c*4);
        }
        cpa_commit();
    };
    issueB(0); issueB(1); issueB(2);

    // stage A (64 rows x 128 k) into k-major smem, conflict-free STS
    {
        const int row=tid&63, kc0=(tid>>6)*32;
#pragma unroll
        for (int i=0;i<8;++i){
            float4 v = *(const float4*)(src + (size_t)row*ND + kc0 + i*4);
            As[kc0+i*4+0][row]=v.x; As[kc0+i*4+1][row]=v.y;
            As[kc0+i*4+2][row]=v.z; As[kc0+i*4+3][row]=v.w;
        }
    }
    __syncthreads();

    const int rg=tid>>5, cc=(tid&31)*4;
#pragma unroll 1
    for (int e=0;e<NE;++e){
        u64 acc[8][2];
#pragma unroll
        for (int i=0;i<8;++i){ acc[i][0]=0ull; acc[i][1]=0ull; }
#pragma unroll 1
        for (int kt=0;kt<8;++kt){
            const int t=e*8+kt;
            if (t<30) cpa_wait2(); else if (t==30) cpa_wait1(); else cpa_wait0();
            __syncthreads();
            if (t+3<32) issueB(t+3);
#pragma unroll
            for (int kk=0;kk<16;++kk){
                const int gk=kt*16+kk;
                float4 pa0 = *(const float4*)&As[gk][rg*8];
                float4 pa1 = *(const float4*)&As[gk][rg*8+4];
                ulonglong2 bv = *(const ulonglong2*)&Bs[t&3][kk][cc];
                u64 a0=pk2(pa0.x,pa0.x), a1=pk2(pa0.y,pa0.y), a2=pk2(pa0.z,pa0.z), a3=pk2(pa0.w,pa0.w);
                u64 a4=pk2(pa1.x,pa1.x), a5=pk2(pa1.y,pa1.y), a6=pk2(pa1.z,pa1.z), a7=pk2(pa1.w,pa1.w);
                fma2(acc[0][0],a0,bv.x); fma2(acc[0][1],a0,bv.y);
                fma2(acc[1][0],a1,bv.x); fma2(acc[1][1],a1,bv.y);
                fma2(acc[2][0],a2,bv.x); fma2(acc[2][1],a2,bv.y);
                fma2(acc[3][0],a3,bv.x); fma2(acc[3][1],a3,bv.y);
                fma2(acc[4][0],a4,bv.x); fma2(acc[4][1],a4,bv.y);
                fma2(acc[5][0],a5,bv.x); fma2(acc[5][1],a5,bv.y);
                fma2(acc[6][0],a6,bv.x); fma2(acc[6][1],a6,bv.y);
                fma2(acc[7][0],a7,bv.x); fma2(acc[7][1],a7,bv.y);
            }
        }
        const float4 bvv = *(const float4*)(bias0 + e*ND + cc);
#pragma unroll
        for (int i=0;i<8;++i){
            const int s = stile*64 + rg*8 + i;
            float v0,v1,v2,v3;
            upk2(acc[i][0],v0,v1); upk2(acc[i][1],v2,v3);
            *(float4*)(dst + ((size_t)s*NE + e)*ND + cc) =
                make_float4(v0+bvv.x, v1+bvv.y, v2+bvv.z, v3+bvv.w);
        }
    }
}

// ---- kernel 2: fp32 aggregation — 256 threads, 2 warps/SMSP, 8x4 microtile ----
// smem: B ring 4 x (16x128 f32) = 32KB ; A raw 2 x (16x64 f32) = 8KB
__global__ void __launch_bounds__(256) agg_kernel(
    const float* __restrict__ A_in, const float* __restrict__ A_out)
{
    __shared__ __align__(16) float Bs[4][16][128];
    __shared__ __align__(16) float As[2][16][64];

    const int tid=threadIdx.x;
    const int mtile=blockIdx.x, dir=blockIdx.y, b=blockIdx.z;
    const float* Arow = (dir? A_out : A_in) + (size_t)b*SL*KA + (size_t)mtile*64*KA;
    const float* Prow = (dir? g_po : g_pi) + (size_t)b*KA*ND;

    const u32 bbase = smem_u32(&Bs[0][0][0]);
    auto issueB = [&](int t){
        const u32 slot = bbase + (u32)(t&3)*8192;
#pragma unroll
        for (int j=0;j<2;++j){
            const int id=tid*2+j, r=id>>5, c=id&31;
            cpa16(slot + r*512 + c*16, Prow + (size_t)(t*16+r)*ND + c*4);
        }
        cpa_commit();
    };

    // A loader: 64 rows x 16 k per tile; each thread one float4 (row=tid&63, k=(tid>>6)*4)
    const int ar = tid&63, akc = (tid>>6)*4;
    auto stsA = [&](int buf, const float4& p){
        As[buf][akc+0][ar]=p.x; As[buf][akc+1][ar]=p.y;
        As[buf][akc+2][ar]=p.z; As[buf][akc+3][ar]=p.w;
    };

    float4 ra = *(const float4*)(Arow + (size_t)ar*KA + akc);
    issueB(0); issueB(1); issueB(2);
    stsA(0, ra);
    ra = *(const float4*)(Arow + (size_t)ar*KA + 16 + akc);

    const int rg = tid>>5;                 // 8 row groups of 8
    const int cc = (tid&31)*4;             // 32 col groups of 4
    u64 acc[8][2];
#pragma unroll
    for (int i=0;i<8;++i){ acc[i][0]=0ull; acc[i][1]=0ull; }

#pragma unroll 1
    for (int t=0; t<256; ++t){
        if (t<254) cpa_wait2(); else if (t==254) cpa_wait1(); else cpa_wait0();
        __syncthreads();
        if (t+3<256) issueB(t+3);
        if (t+1<256) stsA((t+1)&1, ra);
        if (t+2<256)
            ra = *(const float4*)(Arow + (size_t)ar*KA + (t+2)*16 + akc);
        const int ab=t&1, bs=t&3;
#pragma unroll
        for (int kk=0;kk<16;++kk){
            float4 pa0 = *(const float4*)&As[ab][kk][rg*8];
            float4 pa1 = *(const float4*)&As[ab][kk][rg*8+4];
            ulonglong2 bv = *(const ulonglong2*)&Bs[bs][kk][cc];
            u64 a0=pk2(pa0.x,pa0.x), a1=pk2(pa0.y,pa0.y), a2=pk2(pa0.z,pa0.z), a3=pk2(pa0.w,pa0.w);
            u64 a4=pk2(pa1.x,pa1.x), a5=pk2(pa1.y,pa1.y), a6=pk2(pa1.z,pa1.z), a7=pk2(pa1.w,pa1.w);
            fma2(acc[0][0],a0,bv.x); fma2(acc[0][1],a0,bv.y);
            fma2(acc[1][0],a1,bv.x); fma2(acc[1][1],a1,bv.y);
            fma2(acc[2][0],a2,bv.x); fma2(acc[2][1],a2,bv.y);
            fma2(acc[3][0],a3,bv.x); fma2(acc[3][1],a3,bv.y);
            fma2(acc[4][0],a4,bv.x); fma2(acc[4][1],a4,bv.y);
            fma2(acc[5][0],a5,bv.x); fma2(acc[5][1],a5,bv.y);
            fma2(acc[6][0],a6,bv.x); fma2(acc[6][1],a6,bv.y);
            fma2(acc[7][0],a7,bv.x); fma2(acc[7][1],a7,bv.y);
        }
    }

    float* dst = (dir? g_no : g_ni) + (size_t)b*SL*ND + (size_t)mtile*64*ND;
#pragma unroll
    for (int i=0;i<8;++i){
        float v0,v1,v2,v3;
        upk2(acc[i][0],v0,v1); upk2(acc[i][1],v2,v3);
        *(float4*)(dst + (size_t)(rg*8+i)*ND + cc) = make_float4(v0,v1,v2,v3);
    }
}

// ---- kernel 3: fused GRU update — 32-row tiles, 128 CTAs (verified; untouched) ----
__global__ void __launch_bounds__(128) gru_kernel(
    const float* __restrict__ x,
    const float* __restrict__ W_r, const float* __restrict__ b_r,
    const float* __restrict__ W_z, const float* __restrict__ b_z,
    const float* __restrict__ W_h, const float* __restrict__ b_h,
    float* __restrict__ dout, int use_x, int is_final)
{
    __shared__ GSmem32 s;
    const int stile=blockIdx.x, b=blockIdx.z;
    const size_t base=(size_t)b*SL*ND + (size_t)stile*32*ND;
    const float* ni=g_ni+base; const float* no=g_no+base;
    const float* st=(use_x? x : (const float*)g_st)+base;
    const int tid=threadIdx.x, r0=(tid>>4)*4, c0=(tid&15)*8;

    u64 acc[4][4];
    ZERO_ACC(acc);
    gemm32<24>(ni,no,st,W_r,acc,s.g);

    float stv[4][8];
#pragma unroll
    for (int i=0;i<4;++i){
        float4 p0=*(const float4*)(st+(size_t)(r0+i)*ND+c0);
        float4 p1=*(const float4*)(st+(size_t)(r0+i)*ND+c0+4);
        stv[i][0]=p0.x; stv[i][1]=p0.y; stv[i][2]=p0.z; stv[i][3]=p0.w;
        stv[i][4]=p1.x; stv[i][5]=p1.y; stv[i][6]=p1.z; stv[i][7]=p1.w;
    }
#pragma unroll
    for (int i=0;i<4;++i)
#pragma unroll
        for (int j=0;j<4;++j){
            float v0,v1; upk2(acc[i][j],v0,v1);
            const int c=c0+2*j;
            s.ro[r0+i][c]   = sigm(v0+b_r[c])  *stv[i][2*j];
            s.ro[r0+i][c+1] = sigm(v1+b_r[c+1])*stv[i][2*j+1];
        }
    __syncthreads();

    ZERO_ACC(acc);
    gemm32<24>(ni,no,st,W_z,acc,s.g);
    float zv[4][8];
#pragma unroll
    for (int i=0;i<4;++i)
#pragma unroll
        for (int j=0;j<4;++j){
            float v0,v1; upk2(acc[i][j],v0,v1);
            zv[i][2*j]  =sigm(v0+b_z[c0+2*j]);
            zv[i][2*j+1]=sigm(v1+b_z[c0+2*j+1]);
        }

    ZERO_ACC(acc);
    gemm32<24>(ni,no,(const float*)s.ro,W_h,acc,s.g);

    float* ost = g_st + base;
    float* od  = dout + base;
#pragma unroll
    for (int i=0;i<4;++i){
        float o[8];
#pragma unroll
        for (int j=0;j<4;++j){
            float v0,v1; upk2(acc[i][j],v0,v1);
            float h0=tanhf(v0+b_h[c0+2*j]), h1=tanhf(v1+b_h[c0+2*j+1]);
            o[2*j]  =(1.f-zv[i][2*j])  *stv[i][2*j]  + zv[i][2*j]  *h0;
            o[2*j+1]=(1.f-zv[i][2*j+1])*stv[i][2*j+1] + zv[i][2*j+1]*h1;
        }
        *(float4*)(ost+(size_t)(r0+i)*ND+c0)   = make_float4(o[0],o[1],o[2],o[3]);
        *(float4*)(ost+(size_t)(r0+i)*ND+c0+4) = make_float4(o[4],o[5],o[6],o[7]);
        if (is_final){
            *(float4*)(od+(size_t)(r0+i)*ND+c0)   = make_float4(o[0],o[1],o[2],o[3]);
            *(float4*)(od+(size_t)(r0+i)*ND+c0+4) = make_float4(o[4],o[5],o[6],o[7]);
        }
    }
}

extern "C" void kernel_launch(void* const* d_in, const int* in_sizes, int n_in,
                              void* d_out, int out_size)
{
    const float* x      = (const float*)d_in[0];
    const float* A_in   = (const float*)d_in[1];
    const float* A_out  = (const float*)d_in[2];
    const float* W_ein  = (const float*)d_in[3];
    const float* b_ein  = (const float*)d_in[4];
    const float* W_eout = (const float*)d_in[5];
    const float* b_eout = (const float*)d_in[6];
    const float* W_r    = (const float*)d_in[7];
    const float* b_r    = (const float*)d_in[8];
    const float* W_z    = (const float*)d_in[9];
    const float* b_z    = (const float*)d_in[10];
    const float* W_h    = (const float*)d_in[11];
    const float* b_h    = (const float*)d_in[12];
    float* out = (float*)d_out;

    cudaFuncSetAttribute(proj_kernel, cudaFuncAttributeMaxDynamicSharedMemorySize, PROJ_SMEM);

    for (int step=0; step<5; ++step){
        const int use_x = (step==0), fin = (step==4);
        proj_kernel<<<dim3(16,2,4),256,PROJ_SMEM>>>(x, W_ein,b_ein,W_eout,b_eout, use_x);
        agg_kernel <<<dim3(16,2,4),256>>>(A_in, A_out);
        gru_kernel <<<dim3(32,1,4),128>>>(x, W_r,b_r,W_z,b_z,W_h,b_h, out, use_x, fin);
    }
}

// round 14
// speedup vs baseline: 1.0772x; 1.0772x over previous
#include <cuda_runtime.h>
#include <cuda_bf16.h>

#define SL 1024
#define NE 4
#define ND 128
#define NBATCH 4
#define KA (SL*NE)

typedef unsigned long long u64;
typedef unsigned int u32;

// ---- scratch (no allocs allowed) ----
__device__ __align__(128) float g_pi[(size_t)NBATCH*KA*ND];
__device__ __align__(128) float g_po[(size_t)NBATCH*KA*ND];
__device__ __align__(128) float g_ni[(size_t)NBATCH*SL*ND];
__device__ __align__(128) float g_no[(size_t)NBATCH*SL*ND];
__device__ __align__(128) float g_st[(size_t)NBATCH*SL*ND];

// ---- packed f32x2 helpers ----
__device__ __forceinline__ u64 pk2(float a, float b){
    u64 r; asm("mov.b64 %0,{%1,%2};":"=l"(r):"r"(__float_as_uint(a)),"r"(__float_as_uint(b))); return r;
}
__device__ __forceinline__ void upk2(u64 v, float&a, float&b){
    u32 lo,hi; asm("mov.b64 {%0,%1},%2;":"=r"(lo),"=r"(hi):"l"(v));
    a=__uint_as_float(lo); b=__uint_as_float(hi);
}
__device__ __forceinline__ void fma2(u64&d, u64 a, u64 b){
    asm("fma.rn.f32x2 %0,%1,%2,%0;":"+l"(d):"l"(a),"l"(b));
}
__device__ __forceinline__ float sigm(float v){ return 1.f/(1.f+__expf(-v)); }

__device__ __forceinline__ u32 smem_u32(const void* p){
    u32 a; asm("{ .reg .u64 t; cvta.to.shared.u64 t,%1; cvt.u32.u64 %0,t; }":"=r"(a):"l"(p));
    return a;
}
__device__ __forceinline__ void cpa16(u32 dst, const void* src){
    asm volatile("cp.async.cg.shared.global [%0],[%1],16;"::"r"(dst),"l"(src));
}
__device__ __forceinline__ void cpa_commit(){ asm volatile("cp.async.commit_group;"); }
__device__ __forceinline__ void cpa_wait0(){ asm volatile("cp.async.wait_group 0;"); }
__device__ __forceinline__ void cpa_wait1(){ asm volatile("cp.async.wait_group 1;"); }
__device__ __forceinline__ void cpa_wait2(){ asm volatile("cp.async.wait_group 2;"); }

// gru smem: RZ layout's first two fields alias the plain 1-B layout.
struct Smem32   { u64 A2[16][32]; float Bs[16][128]; };                      // 12 KB
struct Smem32RZ { u64 A2[16][32]; float Br[16][128]; float Bz[16][128]; };   // 20 KB
struct GSmem32  { Smem32RZ g; float ro[32][ND]; };                           // 36 KB

// ---- 32-row FFMA2 core, single B (h-gate; verified round 12; untouched) ----
template<int NT>
__device__ __forceinline__ void gemm32(
    const float* a0, const float* a1, const float* a2,
    const float* __restrict__ Bmat, u64 (&acc)[4][4], Smem32& sm)
{
    const int tid=threadIdx.x;
    const int r0=(tid>>4)*4, c0=(tid&15)*8;
    const int arow=tid>>2, ac=(tid&3)*4;
    const int bw=tid>>5, bc=(tid&31)*4;
    float4 ra,rb0,rb1,rb2,rb3;
    ra  = *(const float4*)(a0 + (size_t)arow*ND + ac);
    rb0 = *(const float4*)(Bmat + bw*ND + bc);
    rb1 = *(const float4*)(Bmat + (bw+4)*ND + bc);
    rb2 = *(const float4*)(Bmat + (bw+8)*ND + bc);
    rb3 = *(const float4*)(Bmat + (bw+12)*ND + bc);
#pragma unroll 1
    for (int kt=0; kt<NT; ++kt){
        sm.A2[ac+0][arow]=pk2(ra.x,ra.x); sm.A2[ac+1][arow]=pk2(ra.y,ra.y);
        sm.A2[ac+2][arow]=pk2(ra.z,ra.z); sm.A2[ac+3][arow]=pk2(ra.w,ra.w);
        *(float4*)&sm.Bs[bw][bc]   =rb0;
        *(float4*)&sm.Bs[bw+4][bc] =rb1;
        *(float4*)&sm.Bs[bw+8][bc] =rb2;
        *(float4*)&sm.Bs[bw+12][bc]=rb3;
        __syncthreads();
        if (kt+1<NT){
            const int kn=kt+1;
            const float* ap=(kn<8)?a0:((kn<16)?a1:a2);
            const int off=(kn&7)*16;
            ra = *(const float4*)(ap + (size_t)arow*ND + off + ac);
            const float* bp = Bmat + (size_t)kn*16*ND;
            rb0 = *(const float4*)(bp + bw*ND + bc);
            rb1 = *(const float4*)(bp + (bw+4)*ND + bc);
            rb2 = *(const float4*)(bp + (bw+8)*ND + bc);
            rb3 = *(const float4*)(bp + (bw+12)*ND + bc);
        }
#pragma unroll
        for (int kk=0;kk<16;++kk){
            u64 a0v=sm.A2[kk][r0],a1v=sm.A2[kk][r0+1],a2v=sm.A2[kk][r0+2],a3v=sm.A2[kk][r0+3];
            ulonglong2 b01=*(const ulonglong2*)&sm.Bs[kk][c0];
            ulonglong2 b23=*(const ulonglong2*)&sm.Bs[kk][c0+4];
            fma2(acc[0][0],a0v,b01.x); fma2(acc[0][1],a0v,b01.y); fma2(acc[0][2],a0v,b23.x); fma2(acc[0][3],a0v,b23.y);
            fma2(acc[1][0],a1v,b01.x); fma2(acc[1][1],a1v,b01.y); fma2(acc[1][2],a1v,b23.x); fma2(acc[1][3],a1v,b23.y);
            fma2(acc[2][0],a2v,b01.x); fma2(acc[2][1],a2v,b01.y); fma2(acc[2][2],a2v,b23.x); fma2(acc[2][3],a2v,b23.y);
            fma2(acc[3][0],a3v,b01.x); fma2(acc[3][1],a3v,b01.y); fma2(acc[3][2],a3v,b23.x); fma2(acc[3][3],a3v,b23.y);
        }
        __syncthreads();
    }
}

// ---- 32-row FFMA2 core, dual B (fused r+z). Same A staging & k order per gate. ----
template<int NT>
__device__ __forceinline__ void gemm32_rz(
    const float* a0, const float* a1, const float* a2,
    const float* __restrict__ Br, const float* __restrict__ Bz,
    u64 (&accr)[4][4], u64 (&accz)[4][4], Smem32RZ& sm)
{
    const int tid=threadIdx.x;
    const int r0=(tid>>4)*4, c0=(tid&15)*8;
    const int arow=tid>>2, ac=(tid&3)*4;
    const int bw=tid>>5, bc=(tid&31)*4;
    float4 ra, rr0,rr1,rr2,rr3, rz0,rz1,rz2,rz3;
    ra  = *(const float4*)(a0 + (size_t)arow*ND + ac);
    rr0 = *(const float4*)(Br + bw*ND + bc);
    rr1 = *(const float4*)(Br + (bw+4)*ND + bc);
    rr2 = *(const float4*)(Br + (bw+8)*ND + bc);
    rr3 = *(const float4*)(Br + (bw+12)*ND + bc);
    rz0 = *(const float4*)(Bz + bw*ND + bc);
    rz1 = *(const float4*)(Bz + (bw+4)*ND + bc);
    rz2 = *(const float4*)(Bz + (bw+8)*ND + bc);
    rz3 = *(const float4*)(Bz + (bw+12)*ND + bc);
#pragma unroll 1
    for (int kt=0; kt<NT; ++kt){
        sm.A2[ac+0][arow]=pk2(ra.x,ra.x); sm.A2[ac+1][arow]=pk2(ra.y,ra.y);
        sm.A2[ac+2][arow]=pk2(ra.z,ra.z); sm.A2[ac+3][arow]=pk2(ra.w,ra.w);
        *(float4*)&sm.Br[bw][bc]   =rr0;
        *(float4*)&sm.Br[bw+4][bc] =rr1;
        *(float4*)&sm.Br[bw+8][bc] =rr2;
        *(float4*)&sm.Br[bw+12][bc]=rr3;
        *(float4*)&sm.Bz[bw][bc]   =rz0;
        *(float4*)&sm.Bz[bw+4][bc] =rz1;
        *(float4*)&sm.Bz[bw+8][bc] =rz2;
        *(float4*)&sm.Bz[bw+12][bc]=rz3;
        __syncthreads();
        if (kt+1<NT){
            const int kn=kt+1;
            const float* ap=(kn<8)?a0:((kn<16)?a1:a2);
            const int off=(kn&7)*16;
            ra = *(const float4*)(ap + (size_t)arow*ND + off + ac);
            const float* bp = Br + (size_t)kn*16*ND;
            rr0 = *(const float4*)(bp + bw*ND + bc);
            rr1 = *(const float4*)(bp + (bw+4)*ND + bc);
            rr2 = *(const float4*)(bp + (bw+8)*ND + bc);
            rr3 = *(const float4*)(bp + (bw+12)*ND + bc);
            const float* bq = Bz + (size_t)kn*16*ND;
            rz0 = *(const float4*)(bq + bw*ND + bc);
            rz1 = *(const float4*)(bq + (bw+4)*ND + bc);
            rz2 = *(const float4*)(bq + (bw+8)*ND + bc);
            rz3 = *(const float4*)(bq + (bw+12)*ND + bc);
        }
#pragma unroll
        for (int kk=0;kk<16;++kk){
            u64 a0v=sm.A2[kk][r0],a1v=sm.A2[kk][r0+1],a2v=sm.A2[kk][r0+2],a3v=sm.A2[kk][r0+3];
            ulonglong2 r01=*(const ulonglong2*)&sm.Br[kk][c0];
            ulonglong2 r23=*(const ulonglong2*)&sm.Br[kk][c0+4];
            fma2(accr[0][0],a0v,r01.x); fma2(accr[0][1],a0v,r01.y); fma2(accr[0][2],a0v,r23.x); fma2(accr[0][3],a0v,r23.y);
            fma2(accr[1][0],a1v,r01.x); fma2(accr[1][1],a1v,r01.y); fma2(accr[1][2],a1v,r23.x); fma2(accr[1][3],a1v,r23.y);
            fma2(accr[2][0],a2v,r01.x); fma2(accr[2][1],a2v,r01.y); fma2(accr[2][2],a2v,r23.x); fma2(accr[2][3],a2v,r23.y);
            fma2(accr[3][0],a3v,r01.x); fma2(accr[3][1],a3v,r01.y); fma2(accr[3][2],a3v,r23.x); fma2(accr[3][3],a3v,r23.y);
            ulonglong2 z01=*(const ulonglong2*)&sm.Bz[kk][c0];
            ulonglong2 z23=*(const ulonglong2*)&sm.Bz[kk][c0+4];
            fma2(accz[0][0],a0v,z01.x); fma2(accz[0][1],a0v,z01.y); fma2(accz[0][2],a0v,z23.x); fma2(accz[0][3],a0v,z23.y);
            fma2(accz[1][0],a1v,z01.x); fma2(accz[1][1],a1v,z01.y); fma2(accz[1][2],a1v,z23.x); fma2(accz[1][3],a1v,z23.y);
            fma2(accz[2][0],a2v,z01.x); fma2(accz[2][1],a2v,z01.y); fma2(accz[2][2],a2v,z23.x); fma2(accz[2][3],a2v,z23.y);
            fma2(accz[3][0],a3v,z01.x); fma2(accz[3][1],a3v,z01.y); fma2(accz[3][2],a3v,z23.x); fma2(accz[3][3],a3v,z23.y);
        }
        __syncthreads();
    }
}
#define ZERO_ACC(acc) { _Pragma("unroll") for(int i=0;i<4;++i){ _Pragma("unroll") for(int j=0;j<4;++j) acc[i][j]=0ull; } }

// ---- kernel 1: proj — round-13 verified (A staged once, 4 GEMMs/CTA) ----
#define PROJ_SMEM 65536
__global__ void __launch_bounds__(256) proj_kernel(
    const float* __restrict__ x,
    const float* __restrict__ W_ein, const float* __restrict__ b_ein,
    const float* __restrict__ W_eout, const float* __restrict__ b_eout, int use_x)
{
    extern __shared__ char psm[];
    float (*As)[64] = (float(*)[64])psm;
    float (*Bs)[16][128] = (float(*)[16][128])(psm + 32768);
    const u32 bbase = smem_u32(psm + 32768);

    const int tid=threadIdx.x;
    const int stile=blockIdx.x, dir=blockIdx.y, b=blockIdx.z;
    const float* src = (use_x? x : (const float*)g_st) + (size_t)b*SL*ND + (size_t)stile*64*ND;
    const float* Wb   = dir? W_eout : W_ein;
    const float* bias0= dir? b_eout : b_ein;
    float* dst = (dir? g_po : g_pi) + (size_t)b*KA*ND;

    auto issueB = [&](int t){
        const float* bp = Wb + (size_t)(t>>3)*ND*ND + (size_t)(t&7)*16*ND;
        const u32 slot = bbase + (u32)(t&3)*8192;
#pragma unroll
        for (int j=0;j<2;++j){
            const int id=tid*2+j, r=id>>5, c=id&31;
            cpa16(slot + r*512 + c*16, bp + (size_t)r*ND + c*4);
        }
        cpa_commit();
    };
    issueB(0); issueB(1); issueB(2);

    {
        const int row=tid&63, kc0=(tid>>6)*32;
#pragma unroll
        for (int i=0;i<8;++i){
            float4 v = *(const float4*)(src + (size_t)row*ND + kc0 + i*4);
            As[kc0+i*4+0][row]=v.x; As[kc0+i*4+1][row]=v.y;
            As[kc0+i*4+2][row]=v.z; As[kc0+i*4+3][row]=v.w;
        }
    }
    __syncthreads();

    const int rg=tid>>5, cc=(tid&31)*4;
#pragma unroll 1
    for (int e=0;e<NE;++e){
        u64 acc[8][2];
#pragma unroll
        for (int i=0;i<8;++i){ acc[i][0]=0ull; acc[i][1]=0ull; }
#pragma unroll 1
        for (int kt=0;kt<8;++kt){
            const int t=e*8+kt;
            if (t<30) cpa_wait2(); else if (t==30) cpa_wait1(); else cpa_wait0();
            __syncthreads();
            if (t+3<32) issueB(t+3);
#pragma unroll
            for (int kk=0;kk<16;++kk){
                const int gk=kt*16+kk;
                float4 pa0 = *(const float4*)&As[gk][rg*8];
                float4 pa1 = *(const float4*)&As[gk][rg*8+4];
                ulonglong2 bv = *(const ulonglong2*)&Bs[t&3][kk][cc];
                u64 a0=pk2(pa0.x,pa0.x), a1=pk2(pa0.y,pa0.y), a2=pk2(pa0.z,pa0.z), a3=pk2(pa0.w,pa0.w);
                u64 a4=pk2(pa1.x,pa1.x), a5=pk2(pa1.y,pa1.y), a6=pk2(pa1.z,pa1.z), a7=pk2(pa1.w,pa1.w);
                fma2(acc[0][0],a0,bv.x); fma2(acc[0][1],a0,bv.y);
                fma2(acc[1][0],a1,bv.x); fma2(acc[1][1],a1,bv.y);
                fma2(acc[2][0],a2,bv.x); fma2(acc[2][1],a2,bv.y);
                fma2(acc[3][0],a3,bv.x); fma2(acc[3][1],a3,bv.y);
                fma2(acc[4][0],a4,bv.x); fma2(acc[4][1],a4,bv.y);
                fma2(acc[5][0],a5,bv.x); fma2(acc[5][1],a5,bv.y);
                fma2(acc[6][0],a6,bv.x); fma2(acc[6][1],a6,bv.y);
                fma2(acc[7][0],a7,bv.x); fma2(acc[7][1],a7,bv.y);
            }
        }
        const float4 bvv = *(const float4*)(bias0 + e*ND + cc);
#pragma unroll
        for (int i=0;i<8;++i){
            const int s = stile*64 + rg*8 + i;
            float v0,v1,v2,v3;
            upk2(acc[i][0],v0,v1); upk2(acc[i][1],v2,v3);
            *(float4*)(dst + ((size_t)s*NE + e)*ND + cc) =
                make_float4(v0+bvv.x, v1+bvv.y, v2+bvv.z, v3+bvv.w);
        }
    }
}

// ---- kernel 2: fp32 aggregation — round-11 verified 128-thread 8x8 (reverted) ----
__global__ void __launch_bounds__(128,2) agg_kernel(
    const float* __restrict__ A_in, const float* __restrict__ A_out)
{
    __shared__ __align__(16) float Bs[4][16][128];
    __shared__ __align__(16) float As[2][16][64];

    const int tid=threadIdx.x;
    const int mtile=blockIdx.x, dir=blockIdx.y, b=blockIdx.z;
    const float* Arow = (dir? A_out : A_in) + (size_t)b*SL*KA + (size_t)mtile*64*KA;
    const float* Prow = (dir? g_po : g_pi) + (size_t)b*KA*ND;

    const u32 bbase = smem_u32(&Bs[0][0][0]);
    auto issueB = [&](int t){
        const u32 slot = bbase + (u32)(t&3)*8192;
#pragma unroll
        for (int j=0;j<4;++j){
            const int id=tid+j*128, r=id>>5, c=id&31;
            cpa16(slot + r*512 + c*16, Prow + (size_t)(t*16+r)*ND + c*4);
        }
        cpa_commit();
    };

    const int ar = tid&63, akc = (tid>>6)*8;
    auto stsA = [&](int buf, const float4& p0, const float4& p1){
        As[buf][akc+0][ar]=p0.x; As[buf][akc+1][ar]=p0.y;
        As[buf][akc+2][ar]=p0.z; As[buf][akc+3][ar]=p0.w;
        As[buf][akc+4][ar]=p1.x; As[buf][akc+5][ar]=p1.y;
        As[buf][akc+6][ar]=p1.z; As[buf][akc+7][ar]=p1.w;
    };

    float4 ra0 = *(const float4*)(Arow + (size_t)ar*KA + akc);
    float4 ra1 = *(const float4*)(Arow + (size_t)ar*KA + akc + 4);
    issueB(0); issueB(1); issueB(2);
    stsA(0, ra0, ra1);
    ra0 = *(const float4*)(Arow + (size_t)ar*KA + 16 + akc);
    ra1 = *(const float4*)(Arow + (size_t)ar*KA + 16 + akc + 4);

    const int rg = tid>>4;
    const int cA = (tid&15)*4, cB = 64 + cA;
    u64 acc[8][4];
#pragma unroll
    for (int i=0;i<8;++i)
#pragma unroll
        for (int j=0;j<4;++j) acc[i][j]=0ull;

#pragma unroll 1
    for (int t=0; t<256; ++t){
        if (t<254) cpa_wait2(); else if (t==254) cpa_wait1(); else cpa_wait0();
        __syncthreads();
        if (t+3<256) issueB(t+3);
        if (t+1<256) stsA((t+1)&1, ra0, ra1);
        if (t+2<256){
            ra0 = *(const float4*)(Arow + (size_t)ar*KA + (t+2)*16 + akc);
            ra1 = *(const float4*)(Arow + (size_t)ar*KA + (t+2)*16 + akc + 4);
        }
        const int ab=t&1, bs=t&3;
#pragma unroll
        for (int kk=0;kk<16;++kk){
            float4 pa0 = *(const float4*)&As[ab][kk][rg*8];
            float4 pa1 = *(const float4*)&As[ab][kk][rg*8+4];
            ulonglong2 bA = *(const ulonglong2*)&Bs[bs][kk][cA];
            ulonglong2 bB = *(const ulonglong2*)&Bs[bs][kk][cB];
            u64 a0=pk2(pa0.x,pa0.x), a1=pk2(pa0.y,pa0.y), a2=pk2(pa0.z,pa0.z), a3=pk2(pa0.w,pa0.w);
            u64 a4=pk2(pa1.x,pa1.x), a5=pk2(pa1.y,pa1.y), a6=pk2(pa1.z,pa1.z), a7=pk2(pa1.w,pa1.w);
            fma2(acc[0][0],a0,bA.x); fma2(acc[0][1],a0,bA.y); fma2(acc[0][2],a0,bB.x); fma2(acc[0][3],a0,bB.y);
            fma2(acc[1][0],a1,bA.x); fma2(acc[1][1],a1,bA.y); fma2(acc[1][2],a1,bB.x); fma2(acc[1][3],a1,bB.y);
            fma2(acc[2][0],a2,bA.x); fma2(acc[2][1],a2,bA.y); fma2(acc[2][2],a2,bB.x); fma2(acc[2][3],a2,bB.y);
            fma2(acc[3][0],a3,bA.x); fma2(acc[3][1],a3,bA.y); fma2(acc[3][2],a3,bB.x); fma2(acc[3][3],a3,bB.y);
            fma2(acc[4][0],a4,bA.x); fma2(acc[4][1],a4,bA.y); fma2(acc[4][2],a4,bB.x); fma2(acc[4][3],a4,bB.y);
            fma2(acc[5][0],a5,bA.x); fma2(acc[5][1],a5,bA.y); fma2(acc[5][2],a5,bB.x); fma2(acc[5][3],a5,bB.y);
            fma2(acc[6][0],a6,bA.x); fma2(acc[6][1],a6,bA.y); fma2(acc[6][2],a6,bB.x); fma2(acc[6][3],a6,bB.y);
            fma2(acc[7][0],a7,bA.x); fma2(acc[7][1],a7,bA.y); fma2(acc[7][2],a7,bB.x); fma2(acc[7][3],a7,bB.y);
        }
    }

    float* dst = (dir? g_no : g_ni) + (size_t)b*SL*ND + (size_t)mtile*64*ND;
#pragma unroll
    for (int i=0;i<8;++i){
        float* drow = dst + (size_t)(rg*8+i)*ND;
        float v0,v1,v2,v3;
        upk2(acc[i][0],v0,v1); upk2(acc[i][1],v2,v3);
        *(float4*)(drow+cA) = make_float4(v0,v1,v2,v3);
        upk2(acc[i][2],v0,v1); upk2(acc[i][3],v2,v3);
        *(float4*)(drow+cB) = make_float4(v0,v1,v2,v3);
    }
}

// ---- kernel 3: fused GRU — r+z in ONE pass, then h ----
__global__ void __launch_bounds__(128) gru_kernel(
    const float* __restrict__ x,
    const float* __restrict__ W_r, const float* __restrict__ b_r,
    const float* __restrict__ W_z, const float* __restrict__ b_z,
    const float* __restrict__ W_h, const float* __restrict__ b_h,
    float* __restrict__ dout, int use_x, int is_final)
{
    __shared__ GSmem32 s;
    const int stile=blockIdx.x, b=blockIdx.z;
    const size_t base=(size_t)b*SL*ND + (size_t)stile*32*ND;
    const float* ni=g_ni+base; const float* no=g_no+base;
    const float* st=(use_x? x : (const float*)g_st)+base;
    const int tid=threadIdx.x, r0=(tid>>4)*4, c0=(tid&15)*8;

    u64 accr[4][4], accz[4][4];
    ZERO_ACC(accr); ZERO_ACC(accz);
    gemm32_rz<24>(ni,no,st,W_r,W_z,accr,accz,s.g);

    float stv[4][8];
#pragma unroll
    for (int i=0;i<4;++i){
        float4 p0=*(const float4*)(st+(size_t)(r0+i)*ND+c0);
        float4 p1=*(const float4*)(st+(size_t)(r0+i)*ND+c0+4);
        stv[i][0]=p0.x; stv[i][1]=p0.y; stv[i][2]=p0.z; stv[i][3]=p0.w;
        stv[i][4]=p1.x; stv[i][5]=p1.y; stv[i][6]=p1.z; stv[i][7]=p1.w;
    }
    float zv[4][8];
#pragma unroll
    for (int i=0;i<4;++i)
#pragma unroll
        for (int j=0;j<4;++j){
            float v0,v1; upk2(accr[i][j],v0,v1);
            const int c=c0+2*j;
            s.ro[r0+i][c]   = sigm(v0+b_r[c])  *stv[i][2*j];
            s.ro[r0+i][c+1] = sigm(v1+b_r[c+1])*stv[i][2*j+1];
            upk2(accz[i][j],v0,v1);
            zv[i][2*j]  =sigm(v0+b_z[c]);
            zv[i][2*j+1]=sigm(v1+b_z[c+1]);
        }
    __syncthreads();

    u64 acc[4][4];
    ZERO_ACC(acc);
    gemm32<24>(ni,no,(const float*)s.ro,W_h,acc,*(Smem32*)&s.g);

    float* ost = g_st + base;
    float* od  = dout + base;
#pragma unroll
    for (int i=0;i<4;++i){
        float o[8];
#pragma unroll
        for (int j=0;j<4;++j){
            float v0,v1; upk2(acc[i][j],v0,v1);
            float h0=tanhf(v0+b_h[c0+2*j]), h1=tanhf(v1+b_h[c0+2*j+1]);
            o[2*j]  =(1.f-zv[i][2*j])  *stv[i][2*j]  + zv[i][2*j]  *h0;
            o[2*j+1]=(1.f-zv[i][2*j+1])*stv[i][2*j+1] + zv[i][2*j+1]*h1;
        }
        *(float4*)(ost+(size_t)(r0+i)*ND+c0)   = make_float4(o[0],o[1],o[2],o[3]);
        *(float4*)(ost+(size_t)(r0+i)*ND+c0+4) = make_float4(o[4],o[5],o[6],o[7]);
        if (is_final){
            *(float4*)(od+(size_t)(r0+i)*ND+c0)   = make_float4(o[0],o[1],o[2],o[3]);
            *(float4*)(od+(size_t)(r0+i)*ND+c0+4) = make_float4(o[4],o[5],o[6],o[7]);
        }
    }
}

extern "C" void kernel_launch(void* const* d_in, const int* in_sizes, int n_in,
                              void* d_out, int out_size)
{
    const float* x      = (const float*)d_in[0];
    const float* A_in   = (const float*)d_in[1];
    const float* A_out  = (const float*)d_in[2];
    const float* W_ein  = (const float*)d_in[3];
    const float* b_ein  = (const float*)d_in[4];
    const float* W_eout = (const float*)d_in[5];
    const float* b_eout = (const float*)d_in[6];
    const float* W_r    = (const float*)d_in[7];
    const float* b_r    = (const float*)d_in[8];
    const float* W_z    = (const float*)d_in[9];
    const float* b_z    = (const float*)d_in[10];
    const float* W_h    = (const float*)d_in[11];
    const float* b_h    = (const float*)d_in[12];
    float* out = (float*)d_out;

    cudaFuncSetAttribute(proj_kernel, cudaFuncAttributeMaxDynamicSharedMemorySize, PROJ_SMEM);

    for (int step=0; step<5; ++step){
        const int use_x = (step==0), fin = (step==4);
        proj_kernel<<<dim3(16,2,4),256,PROJ_SMEM>>>(x, W_ein,b_ein,W_eout,b_eout, use_x);
        agg_kernel <<<dim3(16,2,4),128>>>(A_in, A_out);
        gru_kernel <<<dim3(32,1,4),128>>>(x, W_r,b_r,W_z,b_z,W_h,b_h, out, use_x, fin);
    }
}

// round 16
// speedup vs baseline: 1.1561x; 1.0732x over previous
#include <cuda_runtime.h>
#include <cuda_bf16.h>

#define SL 1024
#define NE 4
#define ND 128
#define NBATCH 4
#define KA (SL*NE)

typedef unsigned long long u64;
typedef unsigned int u32;

// ---- scratch (no allocs allowed) ----
__device__ __align__(128) float g_pi[(size_t)NBATCH*KA*ND];
__device__ __align__(128) float g_po[(size_t)NBATCH*KA*ND];
__device__ __align__(128) float g_ni[(size_t)NBATCH*SL*ND];
__device__ __align__(128) float g_no[(size_t)NBATCH*SL*ND];
__device__ __align__(128) float g_ni2[(size_t)NBATCH*SL*ND];
__device__ __align__(128) float g_no2[(size_t)NBATCH*SL*ND];
__device__ __align__(128) float g_st[(size_t)NBATCH*SL*ND];

// ---- packed f32x2 helpers ----
__device__ __forceinline__ u64 pk2(float a, float b){
    u64 r; asm("mov.b64 %0,{%1,%2};":"=l"(r):"r"(__float_as_uint(a)),"r"(__float_as_uint(b))); return r;
}
__device__ __forceinline__ void upk2(u64 v, float&a, float&b){
    u32 lo,hi; asm("mov.b64 {%0,%1},%2;":"=r"(lo),"=r"(hi):"l"(v));
    a=__uint_as_float(lo); b=__uint_as_float(hi);
}
__device__ __forceinline__ void fma2(u64&d, u64 a, u64 b){
    asm("fma.rn.f32x2 %0,%1,%2,%0;":"+l"(d):"l"(a),"l"(b));
}
__device__ __forceinline__ float sigm(float v){ return 1.f/(1.f+__expf(-v)); }

__device__ __forceinline__ u32 smem_u32(const void* p){
    u32 a; asm("{ .reg .u64 t; cvta.to.shared.u64 t,%1; cvt.u32.u64 %0,t; }":"=r"(a):"l"(p));
    return a;
}
__device__ __forceinline__ void cpa16(u32 dst, const void* src){
    asm volatile("cp.async.cg.shared.global [%0],[%1],16;"::"r"(dst),"l"(src));
}
__device__ __forceinline__ void cpa_commit(){ asm volatile("cp.async.commit_group;"); }
__device__ __forceinline__ void cpa_wait0(){ asm volatile("cp.async.wait_group 0;"); }
__device__ __forceinline__ void cpa_wait1(){ asm volatile("cp.async.wait_group 1;"); }
__device__ __forceinline__ void cpa_wait2(){ asm volatile("cp.async.wait_group 2;"); }

struct Smem32   { u64 A2[16][32]; float Bs[16][128]; };
struct Smem32RZ { u64 A2[16][32]; float Br[16][128]; float Bz[16][128]; };
struct GSmem32  { Smem32RZ g; float ro[32][ND]; };

// ---- 32-row FFMA2 core, single B (verified; untouched) ----
template<int NT>
__device__ __forceinline__ void gemm32(
    const float* a0, const float* a1, const float* a2,
    const float* __restrict__ Bmat, u64 (&acc)[4][4], Smem32& sm)
{
    const int tid=threadIdx.x;
    const int r0=(tid>>4)*4, c0=(tid&15)*8;
    const int arow=tid>>2, ac=(tid&3)*4;
    const int bw=tid>>5, bc=(tid&31)*4;
    float4 ra,rb0,rb1,rb2,rb3;
    ra  = *(const float4*)(a0 + (size_t)arow*ND + ac);
    rb0 = *(const float4*)(Bmat + bw*ND + bc);
    rb1 = *(const float4*)(Bmat + (bw+4)*ND + bc);
    rb2 = *(const float4*)(Bmat + (bw+8)*ND + bc);
    rb3 = *(const float4*)(Bmat + (bw+12)*ND + bc);
#pragma unroll 1
    for (int kt=0; kt<NT; ++kt){
        sm.A2[ac+0][arow]=pk2(ra.x,ra.x); sm.A2[ac+1][arow]=pk2(ra.y,ra.y);
        sm.A2[ac+2][arow]=pk2(ra.z,ra.z); sm.A2[ac+3][arow]=pk2(ra.w,ra.w);
        *(float4*)&sm.Bs[bw][bc]   =rb0;
        *(float4*)&sm.Bs[bw+4][bc] =rb1;
        *(float4*)&sm.Bs[bw+8][bc] =rb2;
        *(float4*)&sm.Bs[bw+12][bc]=rb3;
        __syncthreads();
        if (kt+1<NT){
            const int kn=kt+1;
            const float* ap=(kn<8)?a0:((kn<16)?a1:a2);
            const int off=(kn&7)*16;
            ra = *(const float4*)(ap + (size_t)arow*ND + off + ac);
            const float* bp = Bmat + (size_t)kn*16*ND;
            rb0 = *(const float4*)(bp + bw*ND + bc);
            rb1 = *(const float4*)(bp + (bw+4)*ND + bc);
            rb2 = *(const float4*)(bp + (bw+8)*ND + bc);
            rb3 = *(const float4*)(bp + (bw+12)*ND + bc);
        }
#pragma unroll
        for (int kk=0;kk<16;++kk){
            u64 a0v=sm.A2[kk][r0],a1v=sm.A2[kk][r0+1],a2v=sm.A2[kk][r0+2],a3v=sm.A2[kk][r0+3];
            ulonglong2 b01=*(const ulonglong2*)&sm.Bs[kk][c0];
            ulonglong2 b23=*(const ulonglong2*)&sm.Bs[kk][c0+4];
            fma2(acc[0][0],a0v,b01.x); fma2(acc[0][1],a0v,b01.y); fma2(acc[0][2],a0v,b23.x); fma2(acc[0][3],a0v,b23.y);
            fma2(acc[1][0],a1v,b01.x); fma2(acc[1][1],a1v,b01.y); fma2(acc[1][2],a1v,b23.x); fma2(acc[1][3],a1v,b23.y);
            fma2(acc[2][0],a2v,b01.x); fma2(acc[2][1],a2v,b01.y); fma2(acc[2][2],a2v,b23.x); fma2(acc[2][3],a2v,b23.y);
            fma2(acc[3][0],a3v,b01.x); fma2(acc[3][1],a3v,b01.y); fma2(acc[3][2],a3v,b23.x); fma2(acc[3][3],a3v,b23.y);
        }
        __syncthreads();
    }
}

// ---- 32-row FFMA2 core, dual B (fused r+z; verified round 14; untouched) ----
template<int NT>
__device__ __forceinline__ void gemm32_rz(
    const float* a0, const float* a1, const float* a2,
    const float* __restrict__ Br, const float* __restrict__ Bz,
    u64 (&accr)[4][4], u64 (&accz)[4][4], Smem32RZ& sm)
{
    const int tid=threadIdx.x;
    const int r0=(tid>>4)*4, c0=(tid&15)*8;
    const int arow=tid>>2, ac=(tid&3)*4;
    const int bw=tid>>5, bc=(tid&31)*4;
    float4 ra, rr0,rr1,rr2,rr3, rz0,rz1,rz2,rz3;
    ra  = *(const float4*)(a0 + (size_t)arow*ND + ac);
    rr0 = *(const float4*)(Br + bw*ND + bc);
    rr1 = *(const float4*)(Br + (bw+4)*ND + bc);
    rr2 = *(const float4*)(Br + (bw+8)*ND + bc);
    rr3 = *(const float4*)(Br + (bw+12)*ND + bc);
    rz0 = *(const float4*)(Bz + bw*ND + bc);
    rz1 = *(const float4*)(Bz + (bw+4)*ND + bc);
    rz2 = *(const float4*)(Bz + (bw+8)*ND + bc);
    rz3 = *(const float4*)(Bz + (bw+12)*ND + bc);
#pragma unroll 1
    for (int kt=0; kt<NT; ++kt){
        sm.A2[ac+0][arow]=pk2(ra.x,ra.x); sm.A2[ac+1][arow]=pk2(ra.y,ra.y);
        sm.A2[ac+2][arow]=pk2(ra.z,ra.z); sm.A2[ac+3][arow]=pk2(ra.w,ra.w);
        *(float4*)&sm.Br[bw][bc]   =rr0;
        *(float4*)&sm.Br[bw+4][bc] =rr1;
        *(float4*)&sm.Br[bw+8][bc] =rr2;
        *(float4*)&sm.Br[bw+12][bc]=rr3;
        *(float4*)&sm.Bz[bw][bc]   =rz0;
        *(float4*)&sm.Bz[bw+4][bc] =rz1;
        *(float4*)&sm.Bz[bw+8][bc] =rz2;
        *(float4*)&sm.Bz[bw+12][bc]=rz3;
        __syncthreads();
        if (kt+1<NT){
            const int kn=kt+1;
            const float* ap=(kn<8)?a0:((kn<16)?a1:a2);
            const int off=(kn&7)*16;
            ra = *(const float4*)(ap + (size_t)arow*ND + off + ac);
            const float* bp = Br + (size_t)kn*16*ND;
            rr0 = *(const float4*)(bp + bw*ND + bc);
            rr1 = *(const float4*)(bp + (bw+4)*ND + bc);
            rr2 = *(const float4*)(bp + (bw+8)*ND + bc);
            rr3 = *(const float4*)(bp + (bw+12)*ND + bc);
            const float* bq = Bz + (size_t)kn*16*ND;
            rz0 = *(const float4*)(bq + bw*ND + bc);
            rz1 = *(const float4*)(bq + (bw+4)*ND + bc);
            rz2 = *(const float4*)(bq + (bw+8)*ND + bc);
            rz3 = *(const float4*)(bq + (bw+12)*ND + bc);
        }
#pragma unroll
        for (int kk=0;kk<16;++kk){
            u64 a0v=sm.A2[kk][r0],a1v=sm.A2[kk][r0+1],a2v=sm.A2[kk][r0+2],a3v=sm.A2[kk][r0+3];
            ulonglong2 r01=*(const ulonglong2*)&sm.Br[kk][c0];
            ulonglong2 r23=*(const ulonglong2*)&sm.Br[kk][c0+4];
            fma2(accr[0][0],a0v,r01.x); fma2(accr[0][1],a0v,r01.y); fma2(accr[0][2],a0v,r23.x); fma2(accr[0][3],a0v,r23.y);
            fma2(accr[1][0],a1v,r01.x); fma2(accr[1][1],a1v,r01.y); fma2(accr[1][2],a1v,r23.x); fma2(accr[1][3],a1v,r23.y);
            fma2(accr[2][0],a2v,r01.x); fma2(accr[2][1],a2v,r01.y); fma2(accr[2][2],a2v,r23.x); fma2(accr[2][3],a2v,r23.y);
            fma2(accr[3][0],a3v,r01.x); fma2(accr[3][1],a3v,r01.y); fma2(accr[3][2],a3v,r23.x); fma2(accr[3][3],a3v,r23.y);
            ulonglong2 z01=*(const ulonglong2*)&sm.Bz[kk][c0];
            ulonglong2 z23=*(const ulonglong2*)&sm.Bz[kk][c0+4];
            fma2(accz[0][0],a0v,z01.x); fma2(accz[0][1],a0v,z01.y); fma2(accz[0][2],a0v,z23.x); fma2(accz[0][3],a0v,z23.y);
            fma2(accz[1][0],a1v,z01.x); fma2(accz[1][1],a1v,z01.y); fma2(accz[1][2],a1v,z23.x); fma2(accz[1][3],a1v,z23.y);
            fma2(accz[2][0],a2v,z01.x); fma2(accz[2][1],a2v,z01.y); fma2(accz[2][2],a2v,z23.x); fma2(accz[2][3],a2v,z23.y);
            fma2(accz[3][0],a3v,z01.x); fma2(accz[3][1],a3v,z01.y); fma2(accz[3][2],a3v,z23.x); fma2(accz[3][3],a3v,z23.y);
        }
        __syncthreads();
    }
}
#define ZERO_ACC(acc) { _Pragma("unroll") for(int i=0;i<4;++i){ _Pragma("unroll") for(int j=0;j<4;++j) acc[i][j]=0ull; } }

// ---- kernel 1: proj (verified round 13; untouched) ----
#define PROJ_SMEM 65536
__global__ void __launch_bounds__(256) proj_kernel(
    const float* __restrict__ x,
    const float* __restrict__ W_ein, const float* __restrict__ b_ein,
    const float* __restrict__ W_eout, const float* __restrict__ b_eout, int use_x)
{
    extern __shared__ char psm[];
    float (*As)[64] = (float(*)[64])psm;
    float (*Bs)[16][128] = (float(*)[16][128])(psm + 32768);
    const u32 bbase = smem_u32(psm + 32768);

    const int tid=threadIdx.x;
    const int stile=blockIdx.x, dir=blockIdx.y, b=blockIdx.z;
    const float* src = (use_x? x : (const float*)g_st) + (size_t)b*SL*ND + (size_t)stile*64*ND;
    const float* Wb   = dir? W_eout : W_ein;
    const float* bias0= dir? b_eout : b_ein;
    float* dst = (dir? g_po : g_pi) + (size_t)b*KA*ND;

    auto issueB = [&](int t){
        const float* bp = Wb + (size_t)(t>>3)*ND*ND + (size_t)(t&7)*16*ND;
        const u32 slot = bbase + (u32)(t&3)*8192;
#pragma unroll
        for (int j=0;j<2;++j){
            const int id=tid*2+j, r=id>>5, c=id&31;
            cpa16(slot + r*512 + c*16, bp + (size_t)r*ND + c*4);
        }
        cpa_commit();
    };
    issueB(0); issueB(1); issueB(2);

    {
        const int row=tid&63, kc0=(tid>>6)*32;
#pragma unroll
        for (int i=0;i<8;++i){
            float4 v = *(const float4*)(src + (size_t)row*ND + kc0 + i*4);
            As[kc0+i*4+0][row]=v.x; As[kc0+i*4+1][row]=v.y;
            As[kc0+i*4+2][row]=v.z; As[kc0+i*4+3][row]=v.w;
        }
    }
    __syncthreads();

    const int rg=tid>>5, cc=(tid&31)*4;
#pragma unroll 1
    for (int e=0;e<NE;++e){
        u64 acc[8][2];
#pragma unroll
        for (int i=0;i<8;++i){ acc[i][0]=0ull; acc[i][1]=0ull; }
#pragma unroll 1
        for (int kt=0;kt<8;++kt){
            const int t=e*8+kt;
            if (t<30) cpa_wait2(); else if (t==30) cpa_wait1(); else cpa_wait0();
            __syncthreads();
            if (t+3<32) issueB(t+3);
#pragma unroll
            for (int kk=0;kk<16;++kk){
                const int gk=kt*16+kk;
                float4 pa0 = *(const float4*)&As[gk][rg*8];
                float4 pa1 = *(const float4*)&As[gk][rg*8+4];
                ulonglong2 bv = *(const ulonglong2*)&Bs[t&3][kk][cc];
                u64 a0=pk2(pa0.x,pa0.x), a1=pk2(pa0.y,pa0.y), a2=pk2(pa0.z,pa0.z), a3=pk2(pa0.w,pa0.w);
                u64 a4=pk2(pa1.x,pa1.x), a5=pk2(pa1.y,pa1.y), a6=pk2(pa1.z,pa1.z), a7=pk2(pa1.w,pa1.w);
                fma2(acc[0][0],a0,bv.x); fma2(acc[0][1],a0,bv.y);
                fma2(acc[1][0],a1,bv.x); fma2(acc[1][1],a1,bv.y);
                fma2(acc[2][0],a2,bv.x); fma2(acc[2][1],a2,bv.y);
                fma2(acc[3][0],a3,bv.x); fma2(acc[3][1],a3,bv.y);
                fma2(acc[4][0],a4,bv.x); fma2(acc[4][1],a4,bv.y);
                fma2(acc[5][0],a5,bv.x); fma2(acc[5][1],a5,bv.y);
                fma2(acc[6][0],a6,bv.x); fma2(acc[6][1],a6,bv.y);
                fma2(acc[7][0],a7,bv.x); fma2(acc[7][1],a7,bv.y);
            }
        }
        const float4 bvv = *(const float4*)(bias0 + e*ND + cc);
#pragma unroll
        for (int i=0;i<8;++i){
            const int s = stile*64 + rg*8 + i;
            float v0,v1,v2,v3;
            upk2(acc[i][0],v0,v1); upk2(acc[i][1],v2,v3);
            *(float4*)(dst + ((size_t)s*NE + e)*ND + cc) =
                make_float4(v0+bvv.x, v1+bvv.y, v2+bvv.z, v3+bvv.w);
        }
    }
}

// ---- kernel 2: agg — round-11 core, SPLIT-K x2 (256 CTAs, 2/SM latency cover) ----
__global__ void __launch_bounds__(128,2) agg_kernel(
    const float* __restrict__ A_in, const float* __restrict__ A_out)
{
    __shared__ __align__(16) float Bs[4][16][128];
    __shared__ __align__(16) float As[2][16][64];

    const int tid=threadIdx.x;
    const int mtile=blockIdx.x>>1, ks=blockIdx.x&1, dir=blockIdx.y, b=blockIdx.z;
    const float* Arow = (dir? A_out : A_in) + (size_t)b*SL*KA + (size_t)mtile*64*KA + (size_t)ks*2048;
    const float* Prow = (dir? g_po : g_pi) + (size_t)b*KA*ND + (size_t)ks*2048*ND;

    const u32 bbase = smem_u32(&Bs[0][0][0]);
    auto issueB = [&](int t){
        const u32 slot = bbase + (u32)(t&3)*8192;
#pragma unroll
        for (int j=0;j<4;++j){
            const int id=tid+j*128, r=id>>5, c=id&31;
            cpa16(slot + r*512 + c*16, Prow + (size_t)(t*16+r)*ND + c*4);
        }
        cpa_commit();
    };

    const int ar = tid&63, akc = (tid>>6)*8;
    auto stsA = [&](int buf, const float4& p0, const float4& p1){
        As[buf][akc+0][ar]=p0.x; As[buf][akc+1][ar]=p0.y;
        As[buf][akc+2][ar]=p0.z; As[buf][akc+3][ar]=p0.w;
        As[buf][akc+4][ar]=p1.x; As[buf][akc+5][ar]=p1.y;
        As[buf][akc+6][ar]=p1.z; As[buf][akc+7][ar]=p1.w;
    };

    float4 ra0 = *(const float4*)(Arow + (size_t)ar*KA + akc);
    float4 ra1 = *(const float4*)(Arow + (size_t)ar*KA + akc + 4);
    issueB(0); issueB(1); issueB(2);
    stsA(0, ra0, ra1);
    ra0 = *(const float4*)(Arow + (size_t)ar*KA + 16 + akc);
    ra1 = *(const float4*)(Arow + (size_t)ar*KA + 16 + akc + 4);

    const int rg = tid>>4;
    const int cA = (tid&15)*4, cB = 64 + cA;
    u64 acc[8][4];
#pragma unroll
    for (int i=0;i<8;++i)
#pragma unroll
        for (int j=0;j<4;++j) acc[i][j]=0ull;

#pragma unroll 1
    for (int t=0; t<128; ++t){
        if (t<126) cpa_wait2(); else if (t==126) cpa_wait1(); else cpa_wait0();
        __syncthreads();
        if (t+3<128) issueB(t+3);
        if (t+1<128) stsA((t+1)&1, ra0, ra1);
        if (t+2<128){
            ra0 = *(const float4*)(Arow + (size_t)ar*KA + (t+2)*16 + akc);
            ra1 = *(const float4*)(Arow + (size_t)ar*KA + (t+2)*16 + akc + 4);
        }
        const int ab=t&1, bs=t&3;
#pragma unroll
        for (int kk=0;kk<16;++kk){
            float4 pa0 = *(const float4*)&As[ab][kk][rg*8];
            float4 pa1 = *(const float4*)&As[ab][kk][rg*8+4];
            ulonglong2 bA = *(const ulonglong2*)&Bs[bs][kk][cA];
            ulonglong2 bB = *(const ulonglong2*)&Bs[bs][kk][cB];
            u64 a0=pk2(pa0.x,pa0.x), a1=pk2(pa0.y,pa0.y), a2=pk2(pa0.z,pa0.z), a3=pk2(pa0.w,pa0.w);
            u64 a4=pk2(pa1.x,pa1.x), a5=pk2(pa1.y,pa1.y), a6=pk2(pa1.z,pa1.z), a7=pk2(pa1.w,pa1.w);
            fma2(acc[0][0],a0,bA.x); fma2(acc[0][1],a0,bA.y); fma2(acc[0][2],a0,bB.x); fma2(acc[0][3],a0,bB.y);
            fma2(acc[1][0],a1,bA.x); fma2(acc[1][1],a1,bA.y); fma2(acc[1][2],a1,bB.x); fma2(acc[1][3],a1,bB.y);
            fma2(acc[2][0],a2,bA.x); fma2(acc[2][1],a2,bA.y); fma2(acc[2][2],a2,bB.x); fma2(acc[2][3],a2,bB.y);
            fma2(acc[3][0],a3,bA.x); fma2(acc[3][1],a3,bA.y); fma2(acc[3][2],a3,bB.x); fma2(acc[3][3],a3,bB.y);
            fma2(acc[4][0],a4,bA.x); fma2(acc[4][1],a4,bA.y); fma2(acc[4][2],a4,bB.x); fma2(acc[4][3],a4,bB.y);
            fma2(acc[5][0],a5,bA.x); fma2(acc[5][1],a5,bA.y); fma2(acc[5][2],a5,bB.x); fma2(acc[5][3],a5,bB.y);
            fma2(acc[6][0],a6,bA.x); fma2(acc[6][1],a6,bA.y); fma2(acc[6][2],a6,bB.x); fma2(acc[6][3],a6,bB.y);
            fma2(acc[7][0],a7,bA.x); fma2(acc[7][1],a7,bA.y); fma2(acc[7][2],a7,bB.x); fma2(acc[7][3],a7,bB.y);
        }
    }

    float* dstb = dir? (ks? g_no2 : g_no) : (ks? g_ni2 : g_ni);
    float* dst = dstb + (size_t)b*SL*ND + (size_t)mtile*64*ND;
#pragma unroll
    for (int i=0;i<8;++i){
        float* drow = dst + (size_t)(rg*8+i)*ND;
        float v0,v1,v2,v3;
        upk2(acc[i][0],v0,v1); upk2(acc[i][1],v2,v3);
        *(float4*)(drow+cA) = make_float4(v0,v1,v2,v3);
        upk2(acc[i][2],v0,v1); upk2(acc[i][3],v2,v3);
        *(float4*)(drow+cB) = make_float4(v0,v1,v2,v3);
    }
}

// ---- kernel 2b: combine split-K partials ----
__global__ void __launch_bounds__(256) fix_kernel()
{
    const size_t n = (size_t)NBATCH*SL*ND/4;   // float4 count
    float4* a = (float4*)(blockIdx.y? g_no : g_ni);
    const float4* p = (const float4*)(blockIdx.y? g_no2 : g_ni2);
    for (size_t i=(size_t)blockIdx.x*blockDim.x+threadIdx.x; i<n; i+=(size_t)gridDim.x*blockDim.x){
        float4 v=a[i], w=p[i];
        a[i]=make_float4(v.x+w.x, v.y+w.y, v.z+w.z, v.w+w.w);
    }
}

// ---- kernel 3: fused GRU (verified round 14; untouched) ----
__global__ void __launch_bounds__(128) gru_kernel(
    const float* __restrict__ x,
    const float* __restrict__ W_r, const float* __restrict__ b_r,
    const float* __restrict__ W_z, const float* __restrict__ b_z,
    const float* __restrict__ W_h, const float* __restrict__ b_h,
    float* __restrict__ dout, int use_x, int is_final)
{
    __shared__ GSmem32 s;
    const int stile=blockIdx.x, b=blockIdx.z;
    const size_t base=(size_t)b*SL*ND + (size_t)stile*32*ND;
    const float* ni=g_ni+base; const float* no=g_no+base;
    const float* st=(use_x? x : (const float*)g_st)+base;
    const int tid=threadIdx.x, r0=(tid>>4)*4, c0=(tid&15)*8;

    u64 accr[4][4], accz[4][4];
    ZERO_ACC(accr); ZERO_ACC(accz);
    gemm32_rz<24>(ni,no,st,W_r,W_z,accr,accz,s.g);

    float stv[4][8];
#pragma unroll
    for (int i=0;i<4;++i){
        float4 p0=*(const float4*)(st+(size_t)(r0+i)*ND+c0);
        float4 p1=*(const float4*)(st+(size_t)(r0+i)*ND+c0+4);
        stv[i][0]=p0.x; stv[i][1]=p0.y; stv[i][2]=p0.z; stv[i][3]=p0.w;
        stv[i][4]=p1.x; stv[i][5]=p1.y; stv[i][6]=p1.z; stv[i][7]=p1.w;
    }
    float zv[4][8];
#pragma unroll
    for (int i=0;i<4;++i)
#pragma unroll
        for (int j=0;j<4;++j){
            float v0,v1; upk2(accr[i][j],v0,v1);
            const int c=c0+2*j;
            s.ro[r0+i][c]   = sigm(v0+b_r[c])  *stv[i][2*j];
            s.ro[r0+i][c+1] = sigm(v1+b_r[c+1])*stv[i][2*j+1];
            upk2(accz[i][j],v0,v1);
            zv[i][2*j]  =sigm(v0+b_z[c]);
            zv[i][2*j+1]=sigm(v1+b_z[c+1]);
        }
    __syncthreads();

    u64 acc[4][4];
    ZERO_ACC(acc);
    gemm32<24>(ni,no,(const float*)s.ro,W_h,acc,*(Smem32*)&s.g);

    float* ost = g_st + base;
    float* od  = dout + base;
#pragma unroll
    for (int i=0;i<4;++i){
        float o[8];
#pragma unroll
        for (int j=0;j<4;++j){
            float v0,v1; upk2(acc[i][j],v0,v1);
            float h0=tanhf(v0+b_h[c0+2*j]), h1=tanhf(v1+b_h[c0+2*j+1]);
            o[2*j]  =(1.f-zv[i][2*j])  *stv[i][2*j]  + zv[i][2*j]  *h0;
            o[2*j+1]=(1.f-zv[i][2*j+1])*stv[i][2*j+1] + zv[i][2*j+1]*h1;
        }
        *(float4*)(ost+(size_t)(r0+i)*ND+c0)   = make_float4(o[0],o[1],o[2],o[3]);
        *(float4*)(ost+(size_t)(r0+i)*ND+c0+4) = make_float4(o[4],o[5],o[6],o[7]);
        if (is_final){
            *(float4*)(od+(size_t)(r0+i)*ND+c0)   = make_float4(o[0],o[1],o[2],o[3]);
            *(float4*)(od+(size_t)(r0+i)*ND+c0+4) = make_float4(o[4],o[5],o[6],o[7]);
        }
    }
}

extern "C" void kernel_launch(void* const* d_in, const int* in_sizes, int n_in,
                              void* d_out, int out_size)
{
    const float* x      = (const float*)d_in[0];
    const float* A_in   = (const float*)d_in[1];
    const float* A_out  = (const float*)d_in[2];
    const float* W_ein  = (const float*)d_in[3];
    const float* b_ein  = (const float*)d_in[4];
    const float* W_eout = (const float*)d_in[5];
    const float* b_eout = (const float*)d_in[6];
    const float* W_r    = (const float*)d_in[7];
    const float* b_r    = (const float*)d_in[8];
    const float* W_z    = (const float*)d_in[9];
    const float* b_z    = (const float*)d_in[10];
    const float* W_h    = (const float*)d_in[11];
    const float* b_h    = (const float*)d_in[12];
    float* out = (float*)d_out;

    cudaFuncSetAttribute(proj_kernel, cudaFuncAttributeMaxDynamicSharedMemorySize, PROJ_SMEM);

    for (int step=0; step<5; ++step){
        const int use_x = (step==0), fin = (step==4);
        proj_kernel<<<dim3(16,2,4),256,PROJ_SMEM>>>(x, W_ein,b_ein,W_eout,b_eout, use_x);
        agg_kernel <<<dim3(32,2,4),128>>>(A_in, A_out);
        fix_kernel <<<dim3(256,2,1),256>>>();
        gru_kernel <<<dim3(32,1,4),128>>>(x, W_r,b_r,W_z,b_z,W_h,b_h, out, use_x, fin);
    }
}